// round 7
// baseline (speedup 1.0000x reference)
#include <cuda_runtime.h>
#include <cuda_bf16.h>
#include <math.h>
#include <stdint.h>

// ---------------------------------------------------------------- shapes
constexpr int Bn = 16, Tn = 512, Hn = 512, Vn = 4096, Ln = 64, Jn = 66;
constexpr int Mn = Bn * Tn;            // 8192 GEMM rows
constexpr int Smax = 2 * Ln + 1;       // 129 CTC states
constexpr float NEGF = -1e30f;
constexpr float LOG2E = 1.4426950408889634f;
constexpr float LN2 = 0.6931471805599453f;

// ---------------------------------------------------------------- scratch
__device__ __nv_bfloat16 g_Abf[(size_t)Mn * Hn];    // 8 MB
__device__ __nv_bfloat16 g_Bbf[(size_t)Vn * Hn];    // 4 MB  W^T [V,K] K-major
__device__ float2        g_part[(size_t)Mn * 128];  // per-row (max,sumexp) partials
__device__ float         g_gath[(size_t)Mn * Jn];   // gathered logits at label ids
__device__ float         g_emit[(size_t)Mn * Jn];   // log2-domain log-probs at label ids
__device__ int           g_rep[Bn * Jn];            // duplicate-label representative
__device__ float         g_ll[Bn];
__device__ int           g_ctr;

// ---------------------------------------------------------------- helpers
__device__ __forceinline__ uint32_t smem_u32(const void* p) {
    uint32_t a;
    asm("{ .reg .u64 t; cvta.to.shared.u64 t, %1; cvt.u32.u64 %0, t; }" : "=r"(a) : "l"(p));
    return a;
}
__device__ __forceinline__ void ldm_x4(uint32_t* r, uint32_t addr) {
    asm volatile("ldmatrix.sync.aligned.m8n8.x4.shared.b16 {%0,%1,%2,%3}, [%4];"
                 : "=r"(r[0]), "=r"(r[1]), "=r"(r[2]), "=r"(r[3]) : "r"(addr));
}
__device__ __forceinline__ void ldm_x2(uint32_t* r, uint32_t addr) {
    asm volatile("ldmatrix.sync.aligned.m8n8.x2.shared.b16 {%0,%1}, [%2];"
                 : "=r"(r[0]), "=r"(r[1]) : "r"(addr));
}
__device__ __forceinline__ void mma_bf16(float* d, const uint32_t* a, const uint32_t* b) {
    asm volatile("mma.sync.aligned.m16n8k16.row.col.f32.bf16.bf16.f32 "
                 "{%0,%1,%2,%3}, {%4,%5,%6,%7}, {%8,%9}, {%0,%1,%2,%3};"
                 : "+f"(d[0]), "+f"(d[1]), "+f"(d[2]), "+f"(d[3])
                 : "r"(a[0]), "r"(a[1]), "r"(a[2]), "r"(a[3]), "r"(b[0]), "r"(b[1]));
}
__device__ __forceinline__ float ex2(float x) {
    float r; asm("ex2.approx.ftz.f32 %0, %1;" : "=f"(r) : "f"(x)); return r;
}
__device__ __forceinline__ float lg2(float x) {
    float r; asm("lg2.approx.f32 %0, %1;" : "=f"(r) : "f"(x)); return r;
}
#define CP_ASYNC16(dst, src) \
    asm volatile("cp.async.cg.shared.global [%0], [%1], 16;" :: "r"(dst), "l"(src) : "memory")
#define CP_COMMIT() asm volatile("cp.async.commit_group;" ::: "memory")
#define CP_WAIT1()  asm volatile("cp.async.wait_group 1;" ::: "memory")

// ---------------------------------------------------------------- fused preprocessing
__global__ __launch_bounds__(256) void prep_kernel(const float* __restrict__ hs,
                                                   const float* __restrict__ W,
                                                   const int* __restrict__ ys) {
    const int bid = blockIdx.x, tid = threadIdx.x;
    if (bid < 4096) {
        size_t i = (size_t)bid * 256 + tid;
        float4 v = ((const float4*)hs)[i];
        __nv_bfloat162 lo = __floats2bfloat162_rn(v.x, v.y);
        __nv_bfloat162 hi = __floats2bfloat162_rn(v.z, v.w);
        uint2 u;
        u.x = *(uint32_t*)&lo;
        u.y = *(uint32_t*)&hi;
        ((uint2*)g_Abf)[i] = u;
    } else if (bid < 6144) {
        __shared__ float tile[32][33];
        const int vb = bid - 4096;
        const int v0 = (vb & 127) * 32, k0 = (vb >> 7) * 32;
        const int tx = tid & 31, ty = tid >> 5;
#pragma unroll
        for (int j = 0; j < 4; j++)
            tile[ty + 8 * j][tx] = W[(size_t)(k0 + ty + 8 * j) * Vn + v0 + tx];
        __syncthreads();
#pragma unroll
        for (int j = 0; j < 4; j++) {
            int vl = ty + 8 * j;
            g_Bbf[(size_t)(v0 + vl) * Hn + k0 + tx] = __float2bfloat16(tile[tx][vl]);
        }
    } else if (bid < 6160) {
        const int b = bid - 6144;
        const int j = tid;
        if (j < 65) {
            const int vid = (j == 0) ? 0 : ys[b * Ln + j - 1];
            int r = j;
            for (int q = 0; q < j; q++) {
                const int vq = (q == 0) ? 0 : ys[b * Ln + q - 1];
                if (vq == vid) { r = q; break; }
            }
            g_rep[b * Jn + j] = r;
        }
    } else {
        if (tid == 0) g_ctr = 0;
    }
}

// ---------------------------------------------------------------- HMMA GEMM, 6-stage cp.async,
// two K-chunks consumed per __syncthreads / wait_group.
constexpr int STAGES = 6;
constexpr int STAGE_BYTES = 16384;
constexpr int GEMM_SMEM = STAGES * STAGE_BYTES;   // 96 KB

__global__ __launch_bounds__(256, 1) void gemm_mma_kernel(const int* __restrict__ ys,
                                                          const float* __restrict__ bias) {
    extern __shared__ __align__(1024) char sm[];
    __shared__ float sbias[128];
    __shared__ int stable[128];

    const int tid = threadIdx.x, w = tid >> 5, lane = tid & 31;
    const int bn = blockIdx.x * 128, bm = blockIdx.y * 128;
    const int b = blockIdx.y >> 2;

    if (tid < 128) { sbias[tid] = bias[bn + tid]; stable[tid] = -1; }
    __syncthreads();
    if (tid == 0) {
        for (int j = 0; j < 65; j++) {
            const int vid = (j == 0) ? 0 : ys[b * Ln + j - 1];
            const int idx = vid - bn;
            if (idx >= 0 && idx < 128 && stable[idx] < 0) stable[idx] = j;
        }
    }

    const int row = tid >> 1, kp = tid & 1;
    const __nv_bfloat16* gA = g_Abf + (size_t)(bm + row) * Hn + kp * 16;
    const __nv_bfloat16* gB = g_Bbf + (size_t)(bn + row) * Hn + kp * 16;
    const uint32_t smb = smem_u32(sm);
    const uint32_t stsA = smb + (uint32_t)(kp * 2) * 2048 + (uint32_t)row * 16;

    const int wm = w >> 2, wn = w & 3;
    const uint32_t aBase = smb + (uint32_t)(wm * 64 + (lane & 15)) * 16 + (uint32_t)(lane >> 4) * 2048;
    const uint32_t bBase = smb + 8192 + (uint32_t)(wn * 32 + (lane & 7)) * 16 + (uint32_t)((lane >> 3) & 1) * 2048;

    float acc[4][4][4];
#pragma unroll
    for (int mi = 0; mi < 4; mi++)
#pragma unroll
        for (int ni = 0; ni < 4; ni++)
#pragma unroll
            for (int e = 0; e < 4; e++) acc[mi][ni][e] = 0.f;

    const int NC = Hn / 32;  // 16 chunks

#define ISSUE_STAGE(slot, c)                                                   \
    do {                                                                       \
        const uint32_t so = (uint32_t)(slot) * STAGE_BYTES;                    \
        _Pragma("unroll")                                                      \
        for (int i = 0; i < 2; i++) {                                          \
            CP_ASYNC16(stsA + so + i * 2048, gA + (c) * 32 + i * 8);           \
            CP_ASYNC16(stsA + so + 8192 + i * 2048, gB + (c) * 32 + i * 8);    \
        }                                                                      \
    } while (0)

#define CONSUME_CHUNK(slot)                                                    \
    do {                                                                       \
        const uint32_t so = (uint32_t)(slot) * STAGE_BYTES;                    \
        _Pragma("unroll")                                                      \
        for (int kk = 0; kk < 2; kk++) {                                       \
            uint32_t aF[4][4], bF[4][2];                                       \
            _Pragma("unroll")                                                  \
            for (int mi = 0; mi < 4; mi++)                                     \
                ldm_x4(aF[mi], aBase + so + kk * 4096 + mi * 256);             \
            _Pragma("unroll")                                                  \
            for (int ni = 0; ni < 4; ni++)                                     \
                ldm_x2(bF[ni], bBase + so + kk * 4096 + ni * 128);             \
            _Pragma("unroll")                                                  \
            for (int mi = 0; mi < 4; mi++)                                     \
                _Pragma("unroll")                                              \
                for (int ni = 0; ni < 4; ni++)                                 \
                    mma_bf16(acc[mi][ni], aF[mi], bF[ni]);                     \
        }                                                                      \
    } while (0)

    // prologue: stages 0,1,2 (3 commit groups)
#pragma unroll
    for (int c = 0; c < 3; c++) { ISSUE_STAGE(c, c); CP_COMMIT(); }

    int slot = 0;  // slot of chunk c (c mod 6)
    for (int c = 0; c < NC; c += 2) {
        CP_WAIT1();         // chunks c, c+1 complete
        __syncthreads();
        // issue chunks c+3, c+4 (slots wrap mod 6; they were consumed >= 1 pair ago)
        {
            int s3 = slot + 3; if (s3 >= STAGES) s3 -= STAGES;
            int s4 = slot + 4; if (s4 >= STAGES) s4 -= STAGES;
            if (c + 3 < NC) ISSUE_STAGE(s3, c + 3);
            CP_COMMIT();
            if (c + 4 < NC) ISSUE_STAGE(s4, c + 4);
            CP_COMMIT();
        }
        CONSUME_CHUNK(slot);
        {
            int s1 = slot + 1; if (s1 >= STAGES) s1 -= STAGES;
            CONSUME_CHUNK(s1);
        }
        slot += 2; if (slot >= STAGES) slot -= STAGES;
    }

    // ---- fused epilogue
    const int tq = lane >> 2, lq = lane & 3;
#pragma unroll
    for (int mi = 0; mi < 4; mi++) {
#pragma unroll
        for (int h = 0; h < 2; h++) {
            const int rloc = wm * 64 + mi * 16 + h * 8 + tq;
            const size_t grow = (size_t)(bm + rloc);
            float v[8];
            float mx = -3.4e38f;
#pragma unroll
            for (int ni = 0; ni < 4; ni++)
#pragma unroll
                for (int e = 0; e < 2; e++) {
                    float f = acc[mi][ni][h * 2 + e] + sbias[wn * 32 + ni * 8 + lq * 2 + e];
                    v[ni * 2 + e] = f;
                    mx = fmaxf(mx, f);
                }
            float sum = 0.f;
#pragma unroll
            for (int i = 0; i < 8; i++) sum += __expf(v[i] - mx);
#pragma unroll
            for (int o = 1; o <= 2; o <<= 1) {
                float mo = __shfl_xor_sync(0xffffffffu, mx, o);
                float so2 = __shfl_xor_sync(0xffffffffu, sum, o);
                float m2 = fmaxf(mx, mo);
                sum = sum * __expf(mx - m2) + so2 * __expf(mo - m2);
                mx = m2;
            }
            if (lq == 0)
                g_part[grow * 128 + blockIdx.x * 4 + wn] = make_float2(mx, sum);
#pragma unroll
            for (int ni = 0; ni < 4; ni++)
#pragma unroll
                for (int e = 0; e < 2; e++) {
                    const int cidx = wn * 32 + ni * 8 + lq * 2 + e;
                    const int slotg = stable[cidx];
                    if (slotg >= 0) g_gath[grow * Jn + slotg] = v[ni * 2 + e];
                }
        }
    }
}

// ---------------------------------------------------------------- LSE reduce + emit (log2 domain)
__global__ __launch_bounds__(256) void lse_emit_kernel() {
    const int warp = threadIdx.x >> 5, lane = threadIdx.x & 31;
    const size_t row = (size_t)blockIdx.x * 8 + warp;
    const int b = (int)(row >> 9);
    float2 p[4];
#pragma unroll
    for (int i = 0; i < 4; i++) p[i] = g_part[row * 128 + lane + 32 * i];
    float m = fmaxf(fmaxf(p[0].x, p[1].x), fmaxf(p[2].x, p[3].x));
#pragma unroll
    for (int o = 16; o > 0; o >>= 1) m = fmaxf(m, __shfl_xor_sync(0xffffffffu, m, o));
    float s = 0.f;
#pragma unroll
    for (int i = 0; i < 4; i++) s += p[i].y * __expf(p[i].x - m);
#pragma unroll
    for (int o = 16; o > 0; o >>= 1) s += __shfl_xor_sync(0xffffffffu, s, o);
    const float lse = m + __logf(s);
#pragma unroll
    for (int j = lane; j < 65; j += 32)
        g_emit[row * Jn + j] = (g_gath[row * Jn + g_rep[b * Jn + j]] - lse) * LOG2E;
}

// ---------------------------------------------------------------- CTC DP: halo-6 wavefront, log2 domain
// 5 warps; warp w: lane L (6..31) owns state s = w*26 + L - 6; lanes 0-5 = halo.
// Three DP steps per cross-warp exchange.
__global__ __launch_bounds__(160) void ctc_dp_kernel(const int* __restrict__ ys,
                                                     const int* __restrict__ hlen,
                                                     const int* __restrict__ ylen,
                                                     float* __restrict__ out) {
    extern __shared__ float sem[];   // staged log2-emissions [inlen][Jn]
    __shared__ float sbuf[2][30];    // ping-pong boundary: 6 values per warp
    __shared__ float sal[Smax + 32];

    const int b = blockIdx.x, tid = threadIdx.x;
    const int w = tid >> 5, lane = tid & 31;
    const int s = w * 26 + lane - 6;
    const int inlen = hlen[b];

    // stage emissions for this batch
    {
        const float2* src = (const float2*)(g_emit + (size_t)b * Tn * Jn);
        float2* dst = (float2*)sem;
        const int n2 = inlen * (Jn / 2);
        for (int i = tid; i < n2; i += 160) dst[i] = src[i];
    }

    int jj = 0;
    bool skipv = false;
    if (s >= 0 && s < Smax && (s & 1)) {
        const int li = (s - 1) >> 1;
        jj = li + 1;
        const int lab = ys[b * Ln + li];
        if (s >= 3) skipv = (lab != 0) && (lab != ys[b * Ln + li - 1]);
    }
    __syncthreads();

    float a = (s == 0) ? sem[0] : (s == 1) ? sem[1] : NEGF;
    int pb = 0;
    if (lane >= 26) sbuf[0][w * 6 + lane - 26] = a;
    __syncthreads();

#define DP_STEP(tt)                                                      \
    do {                                                                 \
        const float e = sem[(tt) * Jn + jj];                             \
        const float up1 = __shfl_up_sync(0xffffffffu, a, 1);             \
        const float up2 = __shfl_up_sync(0xffffffffu, a, 2);             \
        const float am2 = skipv ? up2 : NEGF;                            \
        const float m = fmaxf(fmaxf(a, up1), am2);                       \
        a = m + lg2(ex2(a - m) + ex2(up1 - m) + ex2(am2 - m)) + e;       \
    } while (0)

    for (int t = 1; t < inlen; t += 3) {
        if (lane < 6) a = (w > 0) ? sbuf[pb][(w - 1) * 6 + lane] : NEGF;
        DP_STEP(t);
        if (t + 1 < inlen) DP_STEP(t + 1);
        if (t + 2 < inlen) DP_STEP(t + 2);
        pb ^= 1;
        if (lane >= 26) sbuf[pb][w * 6 + lane - 26] = a;
        __syncthreads();
    }

    if (lane >= 6 && s < Smax) sal[s] = a;
    __syncthreads();
    if (tid == 0) {
        const int s2 = 2 * ylen[b];
        const float x = sal[s2], y = sal[s2 - 1];
        const float m = fmaxf(x, y), d = fminf(x, y) - m;
        g_ll[b] = -(m + lg2(1.f + ex2(d))) * LN2;
        __threadfence();
        const int done = atomicAdd(&g_ctr, 1);
        if (done == Bn - 1) {
            float acc = 0.f;
#pragma unroll
            for (int i = 0; i < Bn; i++) acc += g_ll[i];
            out[0] = acc / (float)Bn;
        }
    }
}

// ----------------------------------------------------------------
extern "C" void kernel_launch(void* const* d_in, const int* in_sizes, int n_in,
                              void* d_out, int out_size) {
    const float* hs   = (const float*)d_in[0];
    const int*   hlen = (const int*)d_in[1];
    const int*   ys   = (const int*)d_in[2];
    const int*   ylen = (const int*)d_in[3];
    const float* Wm   = (const float*)d_in[4];
    const float* bias = (const float*)d_in[5];
    float* out = (float*)d_out;

    static bool attrs_set = false;
    if (!attrs_set) {
        cudaFuncSetAttribute(gemm_mma_kernel, cudaFuncAttributeMaxDynamicSharedMemorySize, GEMM_SMEM);
        cudaFuncSetAttribute(ctc_dp_kernel, cudaFuncAttributeMaxDynamicSharedMemorySize, Tn * Jn * 4);
        attrs_set = true;
    }

    prep_kernel<<<6161, 256>>>(hs, Wm, ys);
    gemm_mma_kernel<<<dim3(Vn / 128, Mn / 128), 256, GEMM_SMEM>>>(ys, bias);
    lse_emit_kernel<<<Mn / 8, 256>>>();
    ctc_dp_kernel<<<Bn, 160, Tn * Jn * 4>>>(ys, hlen, ylen, out);
}

// round 8
// speedup vs baseline: 1.2350x; 1.2350x over previous
#include <cuda_runtime.h>
#include <cuda_bf16.h>
#include <cuda_fp16.h>
#include <math.h>
#include <stdint.h>

// ---------------------------------------------------------------- shapes
constexpr int Bn = 16, Tn = 512, Hn = 512, Vn = 4096, Ln = 64, Jn = 66;
constexpr int Mn = Bn * Tn;            // 8192 GEMM rows
constexpr int Smax = 2 * Ln + 1;       // 129 CTC states
constexpr float NEGF = -1e30f;
constexpr float LOG2E = 1.4426950408889634f;
constexpr float LN2 = 0.6931471805599453f;

// ---------------------------------------------------------------- scratch
__device__ __nv_bfloat16 g_Abf[(size_t)Mn * Hn];    // 8 MB
__device__ __nv_bfloat16 g_Bbf[(size_t)Vn * Hn];    // 4 MB  W^T [V,K] K-major
__device__ float2        g_part[(size_t)Mn * 128];  // per-row (max,sumexp) partials
__device__ float         g_gath[(size_t)Mn * Jn];   // gathered logits at label ids
__device__ __half        g_emith[(size_t)Mn * Jn];  // fp16 log2-domain emissions
__device__ int           g_rep[Bn * Jn];            // duplicate-label representative
__device__ float         g_ll[Bn];
__device__ int           g_ctr;

// ---------------------------------------------------------------- helpers
__device__ __forceinline__ uint32_t smem_u32(const void* p) {
    uint32_t a;
    asm("{ .reg .u64 t; cvta.to.shared.u64 t, %1; cvt.u32.u64 %0, t; }" : "=r"(a) : "l"(p));
    return a;
}
__device__ __forceinline__ void ldm_x4(uint32_t* r, uint32_t addr) {
    asm volatile("ldmatrix.sync.aligned.m8n8.x4.shared.b16 {%0,%1,%2,%3}, [%4];"
                 : "=r"(r[0]), "=r"(r[1]), "=r"(r[2]), "=r"(r[3]) : "r"(addr));
}
__device__ __forceinline__ void ldm_x2(uint32_t* r, uint32_t addr) {
    asm volatile("ldmatrix.sync.aligned.m8n8.x2.shared.b16 {%0,%1}, [%2];"
                 : "=r"(r[0]), "=r"(r[1]) : "r"(addr));
}
__device__ __forceinline__ void mma_bf16(float* d, const uint32_t* a, const uint32_t* b) {
    asm volatile("mma.sync.aligned.m16n8k16.row.col.f32.bf16.bf16.f32 "
                 "{%0,%1,%2,%3}, {%4,%5,%6,%7}, {%8,%9}, {%0,%1,%2,%3};"
                 : "+f"(d[0]), "+f"(d[1]), "+f"(d[2]), "+f"(d[3])
                 : "r"(a[0]), "r"(a[1]), "r"(a[2]), "r"(a[3]), "r"(b[0]), "r"(b[1]));
}
__device__ __forceinline__ float ex2(float x) {
    float r; asm("ex2.approx.ftz.f32 %0, %1;" : "=f"(r) : "f"(x)); return r;
}
__device__ __forceinline__ float lg2(float x) {
    float r; asm("lg2.approx.f32 %0, %1;" : "=f"(r) : "f"(x)); return r;
}
#define CP_ASYNC16(dst, src) \
    asm volatile("cp.async.cg.shared.global [%0], [%1], 16;" :: "r"(dst), "l"(src) : "memory")
#define CP_COMMIT() asm volatile("cp.async.commit_group;" ::: "memory")
#define CP_WAIT2()  asm volatile("cp.async.wait_group 2;" ::: "memory")

// ---------------------------------------------------------------- fused preprocessing
__global__ __launch_bounds__(256) void prep_kernel(const float* __restrict__ hs,
                                                   const float* __restrict__ W,
                                                   const int* __restrict__ ys) {
    const int bid = blockIdx.x, tid = threadIdx.x;
    if (bid < 4096) {
        size_t i = (size_t)bid * 256 + tid;
        float4 v = ((const float4*)hs)[i];
        __nv_bfloat162 lo = __floats2bfloat162_rn(v.x, v.y);
        __nv_bfloat162 hi = __floats2bfloat162_rn(v.z, v.w);
        uint2 u;
        u.x = *(uint32_t*)&lo;
        u.y = *(uint32_t*)&hi;
        ((uint2*)g_Abf)[i] = u;
    } else if (bid < 6144) {
        __shared__ float tile[32][33];
        const int vb = bid - 4096;
        const int v0 = (vb & 127) * 32, k0 = (vb >> 7) * 32;
        const int tx = tid & 31, ty = tid >> 5;
#pragma unroll
        for (int j = 0; j < 4; j++)
            tile[ty + 8 * j][tx] = W[(size_t)(k0 + ty + 8 * j) * Vn + v0 + tx];
        __syncthreads();
#pragma unroll
        for (int j = 0; j < 4; j++) {
            int vl = ty + 8 * j;
            g_Bbf[(size_t)(v0 + vl) * Hn + k0 + tx] = __float2bfloat16(tile[tx][vl]);
        }
    } else if (bid < 6160) {
        const int b = bid - 6144;
        const int j = tid;
        if (j < 65) {
            const int vid = (j == 0) ? 0 : ys[b * Ln + j - 1];
            int r = j;
            for (int q = 0; q < j; q++) {
                const int vq = (q == 0) ? 0 : ys[b * Ln + q - 1];
                if (vq == vid) { r = q; break; }
            }
            g_rep[b * Jn + j] = r;
        }
    } else {
        if (tid == 0) g_ctr = 0;
    }
}

// ---------------------------------------------------------------- HMMA GEMM, 4-stage cp.async (R6-proven)
constexpr int STAGES = 4;
constexpr int STAGE_BYTES = 16384;
constexpr int GEMM_SMEM = STAGES * STAGE_BYTES;   // 64 KB -> 2 CTAs/SM

__global__ __launch_bounds__(256, 2) void gemm_mma_kernel(const int* __restrict__ ys,
                                                          const float* __restrict__ bias) {
    extern __shared__ __align__(1024) char sm[];
    __shared__ float sbias[128];
    __shared__ int stable[128];

    const int tid = threadIdx.x, w = tid >> 5, lane = tid & 31;
    const int bn = blockIdx.x * 128, bm = blockIdx.y * 128;
    const int b = blockIdx.y >> 2;

    if (tid < 128) { sbias[tid] = bias[bn + tid]; stable[tid] = -1; }
    __syncthreads();
    if (tid == 0) {
        for (int j = 0; j < 65; j++) {
            const int vid = (j == 0) ? 0 : ys[b * Ln + j - 1];
            const int idx = vid - bn;
            if (idx >= 0 && idx < 128 && stable[idx] < 0) stable[idx] = j;
        }
    }

    const int row = tid >> 1, kp = tid & 1;
    const __nv_bfloat16* gA = g_Abf + (size_t)(bm + row) * Hn + kp * 16;
    const __nv_bfloat16* gB = g_Bbf + (size_t)(bn + row) * Hn + kp * 16;
    const uint32_t smb = smem_u32(sm);
    const uint32_t stsA = smb + (uint32_t)(kp * 2) * 2048 + (uint32_t)row * 16;

    const int wm = w >> 2, wn = w & 3;
    const uint32_t aBase = smb + (uint32_t)(wm * 64 + (lane & 15)) * 16 + (uint32_t)(lane >> 4) * 2048;
    const uint32_t bBase = smb + 8192 + (uint32_t)(wn * 32 + (lane & 7)) * 16 + (uint32_t)((lane >> 3) & 1) * 2048;

    float acc[4][4][4];
#pragma unroll
    for (int mi = 0; mi < 4; mi++)
#pragma unroll
        for (int ni = 0; ni < 4; ni++)
#pragma unroll
            for (int e = 0; e < 4; e++) acc[mi][ni][e] = 0.f;

    const int NC = Hn / 32;

#define ISSUE_STAGE(slot, c)                                                   \
    do {                                                                       \
        const uint32_t so = (uint32_t)(slot) * STAGE_BYTES;                    \
        _Pragma("unroll")                                                      \
        for (int i = 0; i < 2; i++) {                                          \
            CP_ASYNC16(stsA + so + i * 2048, gA + (c) * 32 + i * 8);           \
            CP_ASYNC16(stsA + so + 8192 + i * 2048, gB + (c) * 32 + i * 8);    \
        }                                                                      \
    } while (0)

#pragma unroll
    for (int c = 0; c < 3; c++) { ISSUE_STAGE(c, c); CP_COMMIT(); }

    for (int c = 0; c < NC; c++) {
        CP_WAIT2();
        __syncthreads();
        if (c + 3 < NC) ISSUE_STAGE((c + 3) & (STAGES - 1), c + 3);
        CP_COMMIT();

        const uint32_t so = (uint32_t)(c & (STAGES - 1)) * STAGE_BYTES;
#pragma unroll
        for (int kk = 0; kk < 2; kk++) {
            uint32_t aF[4][4], bF[4][2];
#pragma unroll
            for (int mi = 0; mi < 4; mi++)
                ldm_x4(aF[mi], aBase + so + kk * 4096 + mi * 256);
#pragma unroll
            for (int ni = 0; ni < 4; ni++)
                ldm_x2(bF[ni], bBase + so + kk * 4096 + ni * 128);
#pragma unroll
            for (int mi = 0; mi < 4; mi++)
#pragma unroll
                for (int ni = 0; ni < 4; ni++)
                    mma_bf16(acc[mi][ni], aF[mi], bF[ni]);
        }
    }

    const int tq = lane >> 2, lq = lane & 3;
#pragma unroll
    for (int mi = 0; mi < 4; mi++) {
#pragma unroll
        for (int h = 0; h < 2; h++) {
            const int rloc = wm * 64 + mi * 16 + h * 8 + tq;
            const size_t grow = (size_t)(bm + rloc);
            float v[8];
            float mx = -3.4e38f;
#pragma unroll
            for (int ni = 0; ni < 4; ni++)
#pragma unroll
                for (int e = 0; e < 2; e++) {
                    float f = acc[mi][ni][h * 2 + e] + sbias[wn * 32 + ni * 8 + lq * 2 + e];
                    v[ni * 2 + e] = f;
                    mx = fmaxf(mx, f);
                }
            float sum = 0.f;
#pragma unroll
            for (int i = 0; i < 8; i++) sum += __expf(v[i] - mx);
#pragma unroll
            for (int o = 1; o <= 2; o <<= 1) {
                float mo = __shfl_xor_sync(0xffffffffu, mx, o);
                float so2 = __shfl_xor_sync(0xffffffffu, sum, o);
                float m2 = fmaxf(mx, mo);
                sum = sum * __expf(mx - m2) + so2 * __expf(mo - m2);
                mx = m2;
            }
            if (lq == 0)
                g_part[grow * 128 + blockIdx.x * 4 + wn] = make_float2(mx, sum);
#pragma unroll
            for (int ni = 0; ni < 4; ni++)
#pragma unroll
                for (int e = 0; e < 2; e++) {
                    const int cidx = wn * 32 + ni * 8 + lq * 2 + e;
                    const int slot = stable[cidx];
                    if (slot >= 0) g_gath[grow * Jn + slot] = v[ni * 2 + e];
                }
        }
    }
}

// ---------------------------------------------------------------- LSE reduce + emit (fp16, log2 domain)
__global__ __launch_bounds__(256) void lse_emit_kernel() {
    const int warp = threadIdx.x >> 5, lane = threadIdx.x & 31;
    const size_t row = (size_t)blockIdx.x * 8 + warp;
    const int b = (int)(row >> 9);
    float2 p[4];
#pragma unroll
    for (int i = 0; i < 4; i++) p[i] = g_part[row * 128 + lane + 32 * i];
    float m = fmaxf(fmaxf(p[0].x, p[1].x), fmaxf(p[2].x, p[3].x));
#pragma unroll
    for (int o = 16; o > 0; o >>= 1) m = fmaxf(m, __shfl_xor_sync(0xffffffffu, m, o));
    float s = 0.f;
#pragma unroll
    for (int i = 0; i < 4; i++) s += p[i].y * __expf(p[i].x - m);
#pragma unroll
    for (int o = 16; o > 0; o >>= 1) s += __shfl_xor_sync(0xffffffffu, s, o);
    const float lse = m + __logf(s);
#pragma unroll
    for (int j = lane; j < 65; j += 32)
        g_emith[row * Jn + j] = __float2half((g_gath[row * Jn + g_rep[b * Jn + j]] - lse) * LOG2E);
}

// ---------------------------------------------------------------- CTC DP: 2 batches per block, halo-4,
// log2 domain, fp16 staged emissions. Two interleaved independent chains hide MUFU latency.
__global__ __launch_bounds__(160) void ctc_dp_kernel(const int* __restrict__ ys,
                                                     const int* __restrict__ hlen,
                                                     const int* __restrict__ ylen,
                                                     float* __restrict__ out) {
    extern __shared__ __half semh[];   // [2][Tn][Jn] fp16
    __shared__ float sbuf[2][2][20];   // [pingpong][batch][warp*4 + i]
    __shared__ float sal[2][Smax + 12];

    const int tid = threadIdx.x;
    const int w = tid >> 5, lane = tid & 31;
    const int s = w * 28 + lane - 4;
    const int b0 = blockIdx.x, b1 = blockIdx.x + 8;
    const int inlen0 = hlen[b0], inlen1 = hlen[b1];
    const int maxlen = max(inlen0, inlen1);

    // stage emissions for both batches (uint = half2)
    {
        const int n2 = maxlen * (Jn / 2);
        const uint32_t* s0 = (const uint32_t*)(g_emith + (size_t)b0 * Tn * Jn);
        const uint32_t* s1 = (const uint32_t*)(g_emith + (size_t)b1 * Tn * Jn);
        uint32_t* d0 = (uint32_t*)semh;
        uint32_t* d1 = (uint32_t*)(semh + Tn * Jn);
        for (int i = tid; i < n2; i += 160) { d0[i] = s0[i]; d1[i] = s1[i]; }
    }

    int jj0 = 0, jj1 = 0;
    bool sk0 = false, sk1 = false;
    if (s >= 0 && s < Smax && (s & 1)) {
        const int li = (s - 1) >> 1;
        jj0 = li + 1;
        jj1 = li + 1;
        const int la0 = ys[b0 * Ln + li];
        const int la1 = ys[b1 * Ln + li];
        if (s >= 3) {
            sk0 = (la0 != 0) && (la0 != ys[b0 * Ln + li - 1]);
            sk1 = (la1 != 0) && (la1 != ys[b1 * Ln + li - 1]);
        }
    }
    __syncthreads();

    const __half* e0p = semh;
    const __half* e1p = semh + Tn * Jn;
    float a0 = (s == 0) ? __half2float(e0p[0]) : (s == 1) ? __half2float(e0p[1]) : NEGF;
    float a1 = (s == 0) ? __half2float(e1p[0]) : (s == 1) ? __half2float(e1p[1]) : NEGF;
    int pb = 0;
    if (lane >= 28) {
        sbuf[0][0][w * 4 + lane - 28] = a0;
        sbuf[0][1][w * 4 + lane - 28] = a1;
    }
    __syncthreads();

#define DP_STEP2(tt)                                                          \
    do {                                                                      \
        const float e0 = __half2float(e0p[(tt) * Jn + jj0]);                  \
        const float e1 = __half2float(e1p[(tt) * Jn + jj1]);                  \
        const float u10 = __shfl_up_sync(0xffffffffu, a0, 1);                 \
        const float u11 = __shfl_up_sync(0xffffffffu, a1, 1);                 \
        const float u20 = __shfl_up_sync(0xffffffffu, a0, 2);                 \
        const float u21 = __shfl_up_sync(0xffffffffu, a1, 2);                 \
        const float c0 = sk0 ? u20 : NEGF;                                    \
        const float c1 = sk1 ? u21 : NEGF;                                    \
        const float m0 = fmaxf(fmaxf(a0, u10), c0);                           \
        const float m1 = fmaxf(fmaxf(a1, u11), c1);                           \
        const float n0 = m0 + lg2(ex2(a0 - m0) + ex2(u10 - m0) + ex2(c0 - m0)) + e0; \
        const float n1 = m1 + lg2(ex2(a1 - m1) + ex2(u11 - m1) + ex2(c1 - m1)) + e1; \
        a0 = ((tt) < inlen0) ? n0 : a0;                                       \
        a1 = ((tt) < inlen1) ? n1 : a1;                                       \
    } while (0)

    for (int t = 1; t < maxlen; t += 2) {
        if (lane < 4) {
            a0 = (w > 0) ? sbuf[pb][0][(w - 1) * 4 + lane] : NEGF;
            a1 = (w > 0) ? sbuf[pb][1][(w - 1) * 4 + lane] : NEGF;
        }
        DP_STEP2(t);
        if (t + 1 < maxlen) DP_STEP2(t + 1);
        pb ^= 1;
        if (lane >= 28) {
            sbuf[pb][0][w * 4 + lane - 28] = a0;
            sbuf[pb][1][w * 4 + lane - 28] = a1;
        }
        __syncthreads();
    }

    if (lane >= 4 && s < Smax) { sal[0][s] = a0; sal[1][s] = a1; }
    __syncthreads();
    if (tid == 0) {
        {
            const int s2 = 2 * ylen[b0];
            const float x = sal[0][s2], y = sal[0][s2 - 1];
            const float m = fmaxf(x, y), d = fminf(x, y) - m;
            g_ll[b0] = -(m + lg2(1.f + ex2(d))) * LN2;
        }
        {
            const int s2 = 2 * ylen[b1];
            const float x = sal[1][s2], y = sal[1][s2 - 1];
            const float m = fmaxf(x, y), d = fminf(x, y) - m;
            g_ll[b1] = -(m + lg2(1.f + ex2(d))) * LN2;
        }
        __threadfence();
        const int done = atomicAdd(&g_ctr, 1);
        if (done == 7) {
            float acc = 0.f;
#pragma unroll
            for (int i = 0; i < Bn; i++) acc += g_ll[i];
            out[0] = acc / (float)Bn;
        }
    }
}

// ----------------------------------------------------------------
extern "C" void kernel_launch(void* const* d_in, const int* in_sizes, int n_in,
                              void* d_out, int out_size) {
    const float* hs   = (const float*)d_in[0];
    const int*   hlen = (const int*)d_in[1];
    const int*   ys   = (const int*)d_in[2];
    const int*   ylen = (const int*)d_in[3];
    const float* Wm   = (const float*)d_in[4];
    const float* bias = (const float*)d_in[5];
    float* out = (float*)d_out;

    static bool attrs_set = false;
    if (!attrs_set) {
        cudaFuncSetAttribute(gemm_mma_kernel, cudaFuncAttributeMaxDynamicSharedMemorySize, GEMM_SMEM);
        cudaFuncSetAttribute(ctc_dp_kernel, cudaFuncAttributeMaxDynamicSharedMemorySize, 2 * Tn * Jn * 2);
        attrs_set = true;
    }

    prep_kernel<<<6161, 256>>>(hs, Wm, ys);
    gemm_mma_kernel<<<dim3(Vn / 128, Mn / 128), 256, GEMM_SMEM>>>(ys, bias);
    lse_emit_kernel<<<Mn / 8, 256>>>();
    ctc_dp_kernel<<<8, 160, 2 * Tn * Jn * 2>>>(ys, hlen, ylen, out);
}